// round 14
// baseline (speedup 1.0000x reference)
#include <cuda_runtime.h>
#include <cuda_fp16.h>
#include <cstdint>

#define N_NODES 50000
#define N_EDGES 800000
#define DIM     128
#define N_LAYERS 3
#define N_GRAPHS 128
#define TOT_E   (N_EDGES + N_NODES)   // edges + self loops
#define XS_COLS (DIM * N_LAYERS)      // 384
#define POOL_ELEMS (N_GRAPHS * XS_COLS)
#define NBLK    196                   // ceil(N_NODES/256)

#define NCHUNK 4

// ---------------- scratch (device globals; no allocation allowed) ----------
__device__ int   g_scratch[2 * N_NODES];       // [0:N)=deg, [N:2N)=fill
__device__ int   g_rowptr[N_NODES + 1];
__device__ int   g_colidx[TOT_E];
__device__ float g_dinv[N_NODES];
__device__ uint2 g_thA[(size_t)N_NODES * 32];  // fp16 T ping
__device__ uint2 g_thB[(size_t)N_NODES * 32];  // fp16 T pong
__device__ int   g_goff[N_GRAPHS + 1];
__device__ int   g_bsum[NBLK];

// ---------------- packed f32x2 helpers -------------------------------------
__device__ __forceinline__ unsigned long long pack2(float x, float y) {
    unsigned long long r;
    asm("mov.b64 %0, {%1, %2};" : "=l"(r) : "f"(x), "f"(y));
    return r;
}
__device__ __forceinline__ void unpack2(unsigned long long v, float& lo, float& hi) {
    asm("mov.b64 {%0, %1}, %2;" : "=f"(lo), "=f"(hi) : "l"(v));
}
__device__ __forceinline__ void ffma2(unsigned long long& d,
                                      unsigned long long a,
                                      unsigned long long b) {
    asm("fma.rn.f32x2 %0, %1, %2, %0;" : "+l"(d) : "l"(a), "l"(b));
}

// ---------------- CSR build (deg counts EDGES only; +1 self loop in scans) -
__global__ void edge_deg_kernel(const int* __restrict__ ei) {
    int e2 = blockIdx.x * blockDim.x + threadIdx.x;
    if (e2 * 2 < N_EDGES) {
        int2 d = *(const int2*)&ei[N_EDGES + e2 * 2];
        atomicAdd(&g_scratch[d.x], 1);
        if (e2 * 2 + 1 < N_EDGES) atomicAdd(&g_scratch[d.y], 1);
    }
}

// phase A: per-block sums of (deg+1)
__global__ void scanA_kernel() {
    __shared__ int sh[8];
    int i = blockIdx.x * 256 + threadIdx.x;
    int v = (i < N_NODES) ? (g_scratch[i] + 1) : 0;
#pragma unroll
    for (int o = 16; o; o >>= 1) v += __shfl_down_sync(~0u, v, o);
    if ((threadIdx.x & 31) == 0) sh[threadIdx.x >> 5] = v;
    __syncthreads();
    if (threadIdx.x < 8) {
        int s = sh[threadIdx.x];
#pragma unroll
        for (int o = 4; o; o >>= 1) s += __shfl_down_sync(0xffu, s, o);
        if (threadIdx.x == 0) g_bsum[blockIdx.x] = s;
    }
}

// phase C: every block redundantly scans the 196 block sums, then its
// intra-block exclusive scan -> rowptr; also dinv AND the self-loop colidx.
__global__ void scanC_kernel() {
    __shared__ int sh[256];
    __shared__ int bs[256];
    int t = threadIdx.x;
    int i = blockIdx.x * 256 + t;
    bs[t] = (t < NBLK) ? g_bsum[t] : 0;
    int v  = (i < N_NODES) ? (g_scratch[i] + 1) : 0;
    sh[t] = v;
    __syncthreads();
#pragma unroll
    for (int o = 1; o < 256; o <<= 1) {
        int u1 = (t >= o) ? sh[t - o] : 0;
        int u2 = (t >= o) ? bs[t - o] : 0;
        __syncthreads();
        sh[t] += u1;
        bs[t] += u2;
        __syncthreads();
    }
    int base = (blockIdx.x == 0) ? 0 : bs[blockIdx.x - 1];
    if (i < N_NODES) {
        int rp = sh[t] - v + base;
        g_rowptr[i] = rp;
        g_dinv[i]   = rsqrtf((float)v);
        g_colidx[rp] = i;                 // self loop at slot 0 of the row
    }
    if (blockIdx.x == 0 && t == 0) g_rowptr[N_NODES] = TOT_E;
}

// edges only; slot = rowptr[dst] + 1 + fill++
__global__ void fill_kernel(const int* __restrict__ ei) {
    int e = blockIdx.x * blockDim.x + threadIdx.x;
    if (e < N_EDGES) {
        int src = ei[e];
        int dst = ei[N_EDGES + e];
        int pos = g_rowptr[dst] + 1 + atomicAdd(&g_scratch[N_NODES + dst], 1);
        g_colidx[pos] = src;
    }
}

// graph segment offsets via binary search (side stream)
__global__ void goff_kernel(const int* __restrict__ batch) {
    int g = threadIdx.x;
    if (g > N_GRAPHS) return;
    int lo = 0, hi = N_NODES;
    while (lo < hi) {
        int mid = (lo + hi) >> 1;
        if (batch[mid] < g) lo = mid + 1; else hi = mid;
    }
    g_goff[g] = lo;
}

// ------ spmm row helper: relu(dinv*sum dinv[s]*Tin[s] + bias), 4-unrolled --
__device__ __forceinline__ float4 spmm_row(const uint2* __restrict__ th_in,
                                           int gr, int lane,
                                           const float* __restrict__ bias) {
    int e = g_rowptr[gr], end = g_rowptr[gr + 1];
    float4 acc = make_float4(0.f, 0.f, 0.f, 0.f);
    for (; e + 3 < end; e += 4) {
        int s0 = g_colidx[e];
        int s1 = g_colidx[e + 1];
        int s2 = g_colidx[e + 2];
        int s3 = g_colidx[e + 3];
        float d0 = __ldg(&g_dinv[s0]);
        float d1 = __ldg(&g_dinv[s1]);
        float d2 = __ldg(&g_dinv[s2]);
        float d3 = __ldg(&g_dinv[s3]);
        uint2 u0 = th_in[(size_t)s0 * 32 + lane];
        uint2 u1 = th_in[(size_t)s1 * 32 + lane];
        uint2 u2 = th_in[(size_t)s2 * 32 + lane];
        uint2 u3 = th_in[(size_t)s3 * 32 + lane];
        float2 a0 = __half22float2(*(__half2*)&u0.x);
        float2 b0 = __half22float2(*(__half2*)&u0.y);
        float2 a1 = __half22float2(*(__half2*)&u1.x);
        float2 b1 = __half22float2(*(__half2*)&u1.y);
        float2 a2 = __half22float2(*(__half2*)&u2.x);
        float2 b2 = __half22float2(*(__half2*)&u2.y);
        float2 a3 = __half22float2(*(__half2*)&u3.x);
        float2 b3 = __half22float2(*(__half2*)&u3.y);
        acc.x = fmaf(a0.x, d0, fmaf(a1.x, d1, fmaf(a2.x, d2, fmaf(a3.x, d3, acc.x))));
        acc.y = fmaf(a0.y, d0, fmaf(a1.y, d1, fmaf(a2.y, d2, fmaf(a3.y, d3, acc.y))));
        acc.z = fmaf(b0.x, d0, fmaf(b1.x, d1, fmaf(b2.x, d2, fmaf(b3.x, d3, acc.z))));
        acc.w = fmaf(b0.y, d0, fmaf(b1.y, d1, fmaf(b2.y, d2, fmaf(b3.y, d3, acc.w))));
    }
    for (; e < end; e++) {
        int s0 = g_colidx[e];
        float d0 = __ldg(&g_dinv[s0]);
        uint2 u0 = th_in[(size_t)s0 * 32 + lane];
        float2 a0 = __half22float2(*(__half2*)&u0.x);
        float2 b0 = __half22float2(*(__half2*)&u0.y);
        acc.x = fmaf(a0.x, d0, acc.x);
        acc.y = fmaf(a0.y, d0, acc.y);
        acc.z = fmaf(b0.x, d0, acc.z);
        acc.w = fmaf(b0.y, d0, acc.w);
    }
    float dv = g_dinv[gr];
    float4 bb = *(const float4*)&bias[lane * 4];
    float4 o;
    o.x = fmaxf(fmaf(acc.x, dv, bb.x), 0.f);
    o.y = fmaxf(fmaf(acc.y, dv, bb.y), 0.f);
    o.z = fmaxf(fmaf(acc.z, dv, bb.z), 0.f);
    o.w = fmaxf(fmaf(acc.w, dv, bb.w), 0.f);
    return o;
}

// ---------------- GEMM: T = A @ W (f32x2 FFMA, fp16 store), chunked --------
__global__ __launch_bounds__(256, 2)
void gemm_kernel(const float* __restrict__ A, int lda,
                 const float* __restrict__ W, uint2* __restrict__ th_out,
                 int block_base) {
    __shared__ __align__(16) float As[16][132];
    __shared__ __align__(16) float Ws[16][128];
    const int brow = (blockIdx.x + block_base) * 128;
    const int t  = threadIdx.x;
    const int tx = t & 15;
    const int ty = t >> 4;
    unsigned long long acc2[8][4];
#pragma unroll
    for (int i = 0; i < 8; i++)
#pragma unroll
        for (int jp = 0; jp < 4; jp++) acc2[i][jp] = 0ull;

    for (int kc = 0; kc < DIM; kc += 16) {
#pragma unroll
        for (int i = 0; i < 2; i++) {
            int lin = t + i * 256;
            int row = lin >> 2;
            int kg  = lin & 3;
            float4 v = make_float4(0.f, 0.f, 0.f, 0.f);
            int gr = brow + row;
            if (gr < N_NODES)
                v = *(const float4*)&A[(size_t)gr * lda + kc + kg * 4];
            As[kg * 4 + 0][row] = v.x;
            As[kg * 4 + 1][row] = v.y;
            As[kg * 4 + 2][row] = v.z;
            As[kg * 4 + 3][row] = v.w;
        }
#pragma unroll
        for (int i = 0; i < 2; i++) {
            int lin = t + i * 256;
            int kr = lin >> 5;
            int c4 = lin & 31;
            *(float4*)&Ws[kr][c4 * 4] =
                *(const float4*)&W[(kc + kr) * DIM + c4 * 4];
        }
        __syncthreads();
#pragma unroll
        for (int kk = 0; kk < 16; kk++) {
            float a[8];
            unsigned long long w2[4];
#pragma unroll
            for (int i = 0; i < 8; i++) a[i] = As[kk][ty * 8 + i];
#pragma unroll
            for (int jp = 0; jp < 4; jp++)
                w2[jp] = *(const unsigned long long*)&Ws[kk][tx * 8 + jp * 2];
#pragma unroll
            for (int i = 0; i < 8; i++) {
                unsigned long long a2 = pack2(a[i], a[i]);
#pragma unroll
                for (int jp = 0; jp < 4; jp++)
                    ffma2(acc2[i][jp], a2, w2[jp]);
            }
        }
        __syncthreads();
    }
#pragma unroll
    for (int i = 0; i < 8; i++) {
        int gr = brow + ty * 8 + i;
        if (gr < N_NODES) {
            float2 f01, f23, f45, f67;
            unpack2(acc2[i][0], f01.x, f01.y);
            unpack2(acc2[i][1], f23.x, f23.y);
            unpack2(acc2[i][2], f45.x, f45.y);
            unpack2(acc2[i][3], f67.x, f67.y);
            __half2 h0 = __float22half2_rn(f01);
            __half2 h1 = __float22half2_rn(f23);
            __half2 h2 = __float22half2_rn(f45);
            __half2 h3 = __float22half2_rn(f67);
            uint4 st;
            st.x = *(unsigned*)&h0;
            st.y = *(unsigned*)&h1;
            st.z = *(unsigned*)&h2;
            st.w = *(unsigned*)&h3;
            *(uint4*)&th_out[(size_t)gr * 32 + tx * 2] = st;
        }
    }
}

// ------- SpMM with fused pooling: 8 warps = 8 rows per block ---------------
__global__ void spmm_kernel(const float* __restrict__ bias,
                            float* __restrict__ out,
                            const uint2* __restrict__ th_in,
                            int row_base, int n_rows,
                            const int* __restrict__ batch,
                            float* __restrict__ pool_slice) {
    __shared__ float ps[8][128];
    __shared__ int   bg[8];
    const int wid  = threadIdx.x >> 5;
    const int lane = threadIdx.x & 31;
    const int w    = blockIdx.x * 8 + wid;
    const bool valid = (w < n_rows);
    float4 o = make_float4(0.f, 0.f, 0.f, 0.f);
    if (valid) {
        int gr = row_base + w;
        o = spmm_row(th_in, gr, lane, bias);
        *(float4*)&out[(size_t)gr * XS_COLS + lane * 4] = o;
        if (lane == 0) bg[wid] = batch[gr];
    } else if (lane == 0) {
        bg[wid] = -1;
    }
    *(float4*)&ps[wid][lane * 4] = o;
    __syncthreads();
    if (threadIdx.x < 128) {
        int f = threadIdx.x;
        int g0 = bg[0];
        bool uni = (g0 >= 0);
#pragma unroll
        for (int r = 1; r < 8; r++) uni = uni && (bg[r] == g0);
        if (uni) {
            float s = 0.f;
#pragma unroll
            for (int r = 0; r < 8; r++) s += ps[r][f];
            atomicAdd(&pool_slice[(size_t)g0 * XS_COLS + f], s);
        } else {
#pragma unroll
            for (int r = 0; r < 8; r++)
                if (bg[r] >= 0)
                    atomicAdd(&pool_slice[(size_t)bg[r] * XS_COLS + f], ps[r][f]);
        }
    }
}

// ---------------- finalize: divide pool sums by graph counts ---------------
__global__ void finalize_kernel(float* __restrict__ out_pool) {
    int g = blockIdx.x;
    int f = threadIdx.x;      // 0..383
    float cnt = (float)max(g_goff[g + 1] - g_goff[g], 1);
    out_pool[(size_t)g * XS_COLS + f] /= cnt;
}

// ---------------- launch ---------------------------------------------------
extern "C" void kernel_launch(void* const* d_in, const int* in_sizes, int n_in,
                              void* d_out, int out_size) {
    const float* x     = (const float*)d_in[0];
    const int*   ei    = (const int*)d_in[1];     // int32 (JAX x64 disabled)
    const int*   batch = (const int*)d_in[2];     // int32
    const float* W[3] = { (const float*)d_in[3], (const float*)d_in[5],
                          (const float*)d_in[7] };
    const float* B[3] = { (const float*)d_in[4], (const float*)d_in[6],
                          (const float*)d_in[8] };
    float* out_pool = (float*)d_out;
    float* out_xs   = (float*)d_out + POOL_ELEMS;

    // chunk tables: 391 gemm blocks split 98/98/98/97
    static const int ch_blk[NCHUNK]  = {98, 98, 98, 97};
    static const int ch_base[NCHUNK] = {0, 98, 196, 294};

    static cudaStream_t s2 = nullptr;
    static cudaEvent_t evF = nullptr, evJ = nullptr;
    static cudaEvent_t eSp0[NCHUNK], eSp1[NCHUNK];
    static cudaEvent_t eG1 = nullptr, eG2 = nullptr;
    static void *p_scr = nullptr;
    static uint2 *thA = nullptr, *thB = nullptr;
    if (!s2) {
        cudaStreamCreateWithFlags(&s2, cudaStreamNonBlocking);
        cudaEventCreateWithFlags(&evF, cudaEventDisableTiming);
        cudaEventCreateWithFlags(&evJ, cudaEventDisableTiming);
        for (int c = 0; c < NCHUNK; c++) {
            cudaEventCreateWithFlags(&eSp0[c], cudaEventDisableTiming);
            cudaEventCreateWithFlags(&eSp1[c], cudaEventDisableTiming);
        }
        cudaEventCreateWithFlags(&eG1, cudaEventDisableTiming);
        cudaEventCreateWithFlags(&eG2, cudaEventDisableTiming);
        cudaGetSymbolAddress(&p_scr, g_scratch);
        void* p;
        cudaGetSymbolAddress(&p, g_thA); thA = (uint2*)p;
        cudaGetSymbolAddress(&p, g_thB); thB = (uint2*)p;
    }

    const int gemm_blocks = (N_NODES + 127) / 128;           // 391
    const int sp_blk_all = (N_NODES + 7) / 8;                // 6250

    // fork: goff + layer-0 GEMM (independent of CSR) on s2
    cudaEventRecord(evF, 0);
    cudaStreamWaitEvent(s2, evF, 0);
    goff_kernel<<<1, 256, 0, s2>>>(batch);
    gemm_kernel<<<gemm_blocks, 256, 0, s2>>>(x, DIM, W[0], thA, 0);

    // CSR build + pool zero on the capture stream
    cudaMemsetAsync(p_scr, 0, 2 * N_NODES * sizeof(int), 0);
    cudaMemsetAsync(out_pool, 0, POOL_ELEMS * sizeof(float), 0);
    edge_deg_kernel<<<(N_EDGES / 2 + 255) / 256, 256>>>(ei);
    scanA_kernel<<<NBLK, 256>>>();
    scanC_kernel<<<NBLK, 256>>>();
    fill_kernel<<<(N_EDGES + 255) / 256, 256>>>(ei);

    // join gemm0
    cudaEventRecord(evJ, s2);
    cudaStreamWaitEvent(0, evJ, 0);

    // ---- layer 0 spmm (4-chunk, fused pool) + layer 1 gemm pipeline
    for (int c = 0; c < NCHUNK; c++) {
        int rb = ch_base[c] * 128;
        int nr = min(ch_blk[c] * 128, N_NODES - rb);
        spmm_kernel<<<(nr + 7) / 8, 256>>>(B[0], out_xs, thA, rb, nr, batch, out_pool);
        cudaEventRecord(eSp0[c], 0);
        cudaStreamWaitEvent(s2, eSp0[c], 0);
        gemm_kernel<<<ch_blk[c], 256, 0, s2>>>(out_xs, XS_COLS, W[1], thB, ch_base[c]);
    }
    cudaEventRecord(eG1, s2);
    cudaStreamWaitEvent(0, eG1, 0);

    // ---- layer 1 spmm (4-chunk, fused pool) + layer 2 gemm pipeline
    for (int c = 0; c < NCHUNK; c++) {
        int rb = ch_base[c] * 128;
        int nr = min(ch_blk[c] * 128, N_NODES - rb);
        spmm_kernel<<<(nr + 7) / 8, 256>>>(B[1], out_xs + DIM, thB, rb, nr, batch, out_pool + DIM);
        cudaEventRecord(eSp1[c], 0);
        cudaStreamWaitEvent(s2, eSp1[c], 0);
        gemm_kernel<<<ch_blk[c], 256, 0, s2>>>(out_xs + DIM, XS_COLS, W[2], thA, ch_base[c]);
    }
    cudaEventRecord(eG2, s2);
    cudaStreamWaitEvent(0, eG2, 0);

    // ---- layer 2 spmm (fused pool) + finalize
    spmm_kernel<<<sp_blk_all, 256>>>(B[2], out_xs + 2 * DIM, thA, 0, N_NODES, batch, out_pool + 2 * DIM);
    finalize_kernel<<<N_GRAPHS, XS_COLS>>>(out_pool);
}

// round 15
// speedup vs baseline: 1.1391x; 1.1391x over previous
#include <cuda_runtime.h>
#include <cuda_fp16.h>
#include <cstdint>

#define N_NODES 50000
#define N_EDGES 800000
#define DIM     128
#define N_LAYERS 3
#define N_GRAPHS 128
#define TOT_E   (N_EDGES + N_NODES)   // edges + self loops
#define XS_COLS (DIM * N_LAYERS)      // 384
#define POOL_ELEMS (N_GRAPHS * XS_COLS)
#define NBLK    196                   // ceil(N_NODES/256)

// chunking: H0 = first 25088 rows, H1 = rest
#define H0_ROWS   25088
#define H0_GBLK   196
#define H1_ROWS   (N_NODES - H0_ROWS)   // 24912
#define H1_GBLK   195

// ---------------- scratch (device globals; no allocation allowed) ----------
__device__ int   g_scratch[2 * N_NODES];       // [0:N)=deg, [N:2N)=fill
__device__ int   g_rowptr[N_NODES + 1];
__device__ int   g_colidx[TOT_E];
__device__ float g_dinv[N_NODES];
__device__ uint2 g_thA[(size_t)N_NODES * 32];  // fp16 T ping
__device__ uint2 g_thB[(size_t)N_NODES * 32];  // fp16 T pong
__device__ int   g_goff[N_GRAPHS + 1];
__device__ int   g_bsum[NBLK];

// ---------------- packed f32x2 helpers -------------------------------------
__device__ __forceinline__ unsigned long long pack2(float x, float y) {
    unsigned long long r;
    asm("mov.b64 %0, {%1, %2};" : "=l"(r) : "f"(x), "f"(y));
    return r;
}
__device__ __forceinline__ void unpack2(unsigned long long v, float& lo, float& hi) {
    asm("mov.b64 {%0, %1}, %2;" : "=f"(lo), "=f"(hi) : "l"(v));
}
__device__ __forceinline__ void ffma2(unsigned long long& d,
                                      unsigned long long a,
                                      unsigned long long b) {
    asm("fma.rn.f32x2 %0, %1, %2, %0;" : "+l"(d) : "l"(a), "l"(b));
}

// ---------------- CSR build (deg counts EDGES only; +1 self loop in scans) -
__global__ void edge_deg_kernel(const int* __restrict__ ei) {
    int e2 = blockIdx.x * blockDim.x + threadIdx.x;
    if (e2 * 2 < N_EDGES) {
        int2 d = *(const int2*)&ei[N_EDGES + e2 * 2];
        atomicAdd(&g_scratch[d.x], 1);
        if (e2 * 2 + 1 < N_EDGES) atomicAdd(&g_scratch[d.y], 1);
    }
}

// phase A: per-block sums of (deg+1)
__global__ void scanA_kernel() {
    __shared__ int sh[8];
    int i = blockIdx.x * 256 + threadIdx.x;
    int v = (i < N_NODES) ? (g_scratch[i] + 1) : 0;
#pragma unroll
    for (int o = 16; o; o >>= 1) v += __shfl_down_sync(~0u, v, o);
    if ((threadIdx.x & 31) == 0) sh[threadIdx.x >> 5] = v;
    __syncthreads();
    if (threadIdx.x < 8) {
        int s = sh[threadIdx.x];
#pragma unroll
        for (int o = 4; o; o >>= 1) s += __shfl_down_sync(0xffu, s, o);
        if (threadIdx.x == 0) g_bsum[blockIdx.x] = s;
    }
}

// phase C: every block redundantly scans the 196 block sums, then its
// intra-block exclusive scan -> rowptr; also dinv AND the self-loop colidx.
__global__ void scanC_kernel() {
    __shared__ int sh[256];
    __shared__ int bs[256];
    int t = threadIdx.x;
    int i = blockIdx.x * 256 + t;
    bs[t] = (t < NBLK) ? g_bsum[t] : 0;
    int v  = (i < N_NODES) ? (g_scratch[i] + 1) : 0;
    sh[t] = v;
    __syncthreads();
#pragma unroll
    for (int o = 1; o < 256; o <<= 1) {
        int u1 = (t >= o) ? sh[t - o] : 0;
        int u2 = (t >= o) ? bs[t - o] : 0;
        __syncthreads();
        sh[t] += u1;
        bs[t] += u2;
        __syncthreads();
    }
    int base = (blockIdx.x == 0) ? 0 : bs[blockIdx.x - 1];
    if (i < N_NODES) {
        int rp = sh[t] - v + base;
        g_rowptr[i] = rp;
        g_dinv[i]   = rsqrtf((float)v);
        g_colidx[rp] = i;                 // self loop at slot 0 of the row
    }
    if (blockIdx.x == 0 && t == 0) g_rowptr[N_NODES] = TOT_E;
}

// edges only; slot = rowptr[dst] + 1 + fill++
__global__ void fill_kernel(const int* __restrict__ ei) {
    int e = blockIdx.x * blockDim.x + threadIdx.x;
    if (e < N_EDGES) {
        int src = ei[e];
        int dst = ei[N_EDGES + e];
        int pos = g_rowptr[dst] + 1 + atomicAdd(&g_scratch[N_NODES + dst], 1);
        g_colidx[pos] = src;
    }
}

// graph segment offsets via binary search (side stream)
__global__ void goff_kernel(const int* __restrict__ batch) {
    int g = threadIdx.x;
    if (g > N_GRAPHS) return;
    int lo = 0, hi = N_NODES;
    while (lo < hi) {
        int mid = (lo + hi) >> 1;
        if (batch[mid] < g) lo = mid + 1; else hi = mid;
    }
    g_goff[g] = lo;
}

// ------ spmm row helper: relu(dinv*sum dinv[s]*Tin[s] + bias), 4-unrolled --
__device__ __forceinline__ float4 spmm_row(const uint2* __restrict__ th_in,
                                           int gr, int lane,
                                           const float* __restrict__ bias) {
    int e = g_rowptr[gr], end = g_rowptr[gr + 1];
    float4 acc = make_float4(0.f, 0.f, 0.f, 0.f);
    for (; e + 3 < end; e += 4) {
        int s0 = g_colidx[e];
        int s1 = g_colidx[e + 1];
        int s2 = g_colidx[e + 2];
        int s3 = g_colidx[e + 3];
        float d0 = __ldg(&g_dinv[s0]);
        float d1 = __ldg(&g_dinv[s1]);
        float d2 = __ldg(&g_dinv[s2]);
        float d3 = __ldg(&g_dinv[s3]);
        uint2 u0 = th_in[(size_t)s0 * 32 + lane];
        uint2 u1 = th_in[(size_t)s1 * 32 + lane];
        uint2 u2 = th_in[(size_t)s2 * 32 + lane];
        uint2 u3 = th_in[(size_t)s3 * 32 + lane];
        float2 a0 = __half22float2(*(__half2*)&u0.x);
        float2 b0 = __half22float2(*(__half2*)&u0.y);
        float2 a1 = __half22float2(*(__half2*)&u1.x);
        float2 b1 = __half22float2(*(__half2*)&u1.y);
        float2 a2 = __half22float2(*(__half2*)&u2.x);
        float2 b2 = __half22float2(*(__half2*)&u2.y);
        float2 a3 = __half22float2(*(__half2*)&u3.x);
        float2 b3 = __half22float2(*(__half2*)&u3.y);
        acc.x = fmaf(a0.x, d0, fmaf(a1.x, d1, fmaf(a2.x, d2, fmaf(a3.x, d3, acc.x))));
        acc.y = fmaf(a0.y, d0, fmaf(a1.y, d1, fmaf(a2.y, d2, fmaf(a3.y, d3, acc.y))));
        acc.z = fmaf(b0.x, d0, fmaf(b1.x, d1, fmaf(b2.x, d2, fmaf(b3.x, d3, acc.z))));
        acc.w = fmaf(b0.y, d0, fmaf(b1.y, d1, fmaf(b2.y, d2, fmaf(b3.y, d3, acc.w))));
    }
    for (; e < end; e++) {
        int s0 = g_colidx[e];
        float d0 = __ldg(&g_dinv[s0]);
        uint2 u0 = th_in[(size_t)s0 * 32 + lane];
        float2 a0 = __half22float2(*(__half2*)&u0.x);
        float2 b0 = __half22float2(*(__half2*)&u0.y);
        acc.x = fmaf(a0.x, d0, acc.x);
        acc.y = fmaf(a0.y, d0, acc.y);
        acc.z = fmaf(b0.x, d0, acc.z);
        acc.w = fmaf(b0.y, d0, acc.w);
    }
    float dv = g_dinv[gr];
    float4 bb = *(const float4*)&bias[lane * 4];
    float4 o;
    o.x = fmaxf(fmaf(acc.x, dv, bb.x), 0.f);
    o.y = fmaxf(fmaf(acc.y, dv, bb.y), 0.f);
    o.z = fmaxf(fmaf(acc.z, dv, bb.z), 0.f);
    o.w = fmaxf(fmaf(acc.w, dv, bb.w), 0.f);
    return o;
}

// ---------------- GEMM: T = A @ W (f32x2 FFMA, fp16 store), BK=32 ----------
__global__ __launch_bounds__(256, 2)
void gemm_kernel(const float* __restrict__ A, int lda,
                 const float* __restrict__ W, uint2* __restrict__ th_out,
                 int block_base) {
    __shared__ __align__(16) float As[32][132];
    __shared__ __align__(16) float Ws[32][128];
    const int brow = (blockIdx.x + block_base) * 128;
    const int t  = threadIdx.x;
    const int tx = t & 15;
    const int ty = t >> 4;
    unsigned long long acc2[8][4];
#pragma unroll
    for (int i = 0; i < 8; i++)
#pragma unroll
        for (int jp = 0; jp < 4; jp++) acc2[i][jp] = 0ull;

    for (int kc = 0; kc < DIM; kc += 32) {
        // A tile: 128 rows x 32 k, transposed into As[k][row]; 4 float4/thread
#pragma unroll
        for (int i = 0; i < 4; i++) {
            int lin = t + i * 256;          // 0..1023
            int row = lin >> 3;             // 0..127
            int kg  = lin & 7;              // 0..7
            float4 v = make_float4(0.f, 0.f, 0.f, 0.f);
            int gr = brow + row;
            if (gr < N_NODES)
                v = *(const float4*)&A[(size_t)gr * lda + kc + kg * 4];
            As[kg * 4 + 0][row] = v.x;
            As[kg * 4 + 1][row] = v.y;
            As[kg * 4 + 2][row] = v.z;
            As[kg * 4 + 3][row] = v.w;
        }
        // W tile: 32 k-rows x 128 cols; 4 float4/thread
#pragma unroll
        for (int i = 0; i < 4; i++) {
            int lin = t + i * 256;
            int kr = lin >> 5;              // 0..31
            int c4 = lin & 31;
            *(float4*)&Ws[kr][c4 * 4] =
                *(const float4*)&W[(kc + kr) * DIM + c4 * 4];
        }
        __syncthreads();
#pragma unroll
        for (int kk = 0; kk < 32; kk++) {
            float a[8];
            unsigned long long w2[4];
#pragma unroll
            for (int i = 0; i < 8; i++) a[i] = As[kk][ty * 8 + i];
#pragma unroll
            for (int jp = 0; jp < 4; jp++)
                w2[jp] = *(const unsigned long long*)&Ws[kk][tx * 8 + jp * 2];
#pragma unroll
            for (int i = 0; i < 8; i++) {
                unsigned long long a2 = pack2(a[i], a[i]);
#pragma unroll
                for (int jp = 0; jp < 4; jp++)
                    ffma2(acc2[i][jp], a2, w2[jp]);
            }
        }
        __syncthreads();
    }
#pragma unroll
    for (int i = 0; i < 8; i++) {
        int gr = brow + ty * 8 + i;
        if (gr < N_NODES) {
            float2 f01, f23, f45, f67;
            unpack2(acc2[i][0], f01.x, f01.y);
            unpack2(acc2[i][1], f23.x, f23.y);
            unpack2(acc2[i][2], f45.x, f45.y);
            unpack2(acc2[i][3], f67.x, f67.y);
            __half2 h0 = __float22half2_rn(f01);
            __half2 h1 = __float22half2_rn(f23);
            __half2 h2 = __float22half2_rn(f45);
            __half2 h3 = __float22half2_rn(f67);
            uint4 st;
            st.x = *(unsigned*)&h0;
            st.y = *(unsigned*)&h1;
            st.z = *(unsigned*)&h2;
            st.w = *(unsigned*)&h3;
            *(uint4*)&th_out[(size_t)gr * 32 + tx * 2] = st;
        }
    }
}

// ------- SpMM with fused pooling: 8 warps = 8 rows per block ---------------
__global__ void spmm_kernel(const float* __restrict__ bias,
                            float* __restrict__ out,
                            const uint2* __restrict__ th_in,
                            int row_base, int n_rows,
                            const int* __restrict__ batch,
                            float* __restrict__ pool_slice) {
    __shared__ float ps[8][128];
    __shared__ int   bg[8];
    const int wid  = threadIdx.x >> 5;
    const int lane = threadIdx.x & 31;
    const int w    = blockIdx.x * 8 + wid;
    const bool valid = (w < n_rows);
    float4 o = make_float4(0.f, 0.f, 0.f, 0.f);
    if (valid) {
        int gr = row_base + w;
        o = spmm_row(th_in, gr, lane, bias);
        *(float4*)&out[(size_t)gr * XS_COLS + lane * 4] = o;
        if (lane == 0) bg[wid] = batch[gr];
    } else if (lane == 0) {
        bg[wid] = -1;
    }
    *(float4*)&ps[wid][lane * 4] = o;
    __syncthreads();
    if (threadIdx.x < 128) {
        int f = threadIdx.x;
        int g0 = bg[0];
        bool uni = (g0 >= 0);
#pragma unroll
        for (int r = 1; r < 8; r++) uni = uni && (bg[r] == g0);
        if (uni) {
            float s = 0.f;
#pragma unroll
            for (int r = 0; r < 8; r++) s += ps[r][f];
            atomicAdd(&pool_slice[(size_t)g0 * XS_COLS + f], s);
        } else {
#pragma unroll
            for (int r = 0; r < 8; r++)
                if (bg[r] >= 0)
                    atomicAdd(&pool_slice[(size_t)bg[r] * XS_COLS + f], ps[r][f]);
        }
    }
}

// ---------------- finalize: divide pool sums by graph counts ---------------
__global__ void finalize_kernel(float* __restrict__ out_pool) {
    int g = blockIdx.x;
    int f = threadIdx.x;      // 0..383
    float cnt = (float)max(g_goff[g + 1] - g_goff[g], 1);
    out_pool[(size_t)g * XS_COLS + f] /= cnt;
}

// ---------------- launch ---------------------------------------------------
extern "C" void kernel_launch(void* const* d_in, const int* in_sizes, int n_in,
                              void* d_out, int out_size) {
    const float* x     = (const float*)d_in[0];
    const int*   ei    = (const int*)d_in[1];     // int32 (JAX x64 disabled)
    const int*   batch = (const int*)d_in[2];     // int32
    const float* W[3] = { (const float*)d_in[3], (const float*)d_in[5],
                          (const float*)d_in[7] };
    const float* B[3] = { (const float*)d_in[4], (const float*)d_in[6],
                          (const float*)d_in[8] };
    float* out_pool = (float*)d_out;
    float* out_xs   = (float*)d_out + POOL_ELEMS;

    static cudaStream_t s2 = nullptr;
    static cudaEvent_t evF = nullptr, evJ = nullptr;
    static cudaEvent_t eSpA0 = nullptr, eSpA1 = nullptr;
    static cudaEvent_t eG1 = nullptr, eG2 = nullptr;
    static void *p_scr = nullptr;
    static uint2 *thA = nullptr, *thB = nullptr;
    if (!s2) {
        cudaStreamCreateWithFlags(&s2, cudaStreamNonBlocking);
        cudaEventCreateWithFlags(&evF,   cudaEventDisableTiming);
        cudaEventCreateWithFlags(&evJ,   cudaEventDisableTiming);
        cudaEventCreateWithFlags(&eSpA0, cudaEventDisableTiming);
        cudaEventCreateWithFlags(&eSpA1, cudaEventDisableTiming);
        cudaEventCreateWithFlags(&eG1,   cudaEventDisableTiming);
        cudaEventCreateWithFlags(&eG2,   cudaEventDisableTiming);
        cudaGetSymbolAddress(&p_scr, g_scratch);
        void* p;
        cudaGetSymbolAddress(&p, g_thA); thA = (uint2*)p;
        cudaGetSymbolAddress(&p, g_thB); thB = (uint2*)p;
    }

    const int gemm_blocks = (N_NODES + 127) / 128;           // 391
    const int sp_blk_h0 = (H0_ROWS + 7) / 8;                 // 3136
    const int sp_blk_h1 = (H1_ROWS + 7) / 8;                 // 3114
    const int sp_blk_all = (N_NODES + 7) / 8;                // 6250

    // fork: pool-zero + goff + layer-0 GEMM (independent of CSR) on s2
    cudaEventRecord(evF, 0);
    cudaStreamWaitEvent(s2, evF, 0);
    cudaMemsetAsync(out_pool, 0, POOL_ELEMS * sizeof(float), s2);
    goff_kernel<<<1, 256, 0, s2>>>(batch);
    gemm_kernel<<<gemm_blocks, 256, 0, s2>>>(x, DIM, W[0], thA, 0);

    // CSR build on the capture stream
    cudaMemsetAsync(p_scr, 0, 2 * N_NODES * sizeof(int), 0);
    edge_deg_kernel<<<(N_EDGES / 2 + 255) / 256, 256>>>(ei);
    scanA_kernel<<<NBLK, 256>>>();
    scanC_kernel<<<NBLK, 256>>>();
    fill_kernel<<<(N_EDGES + 255) / 256, 256>>>(ei);

    // join gemm0 (also orders pool memset before first spmm)
    cudaEventRecord(evJ, s2);
    cudaStreamWaitEvent(0, evJ, 0);

    // ---- layer 0 spmm (chunked, fused pool) + layer 1 gemm overlap
    spmm_kernel<<<sp_blk_h0, 256>>>(B[0], out_xs, thA, 0, H0_ROWS, batch, out_pool);
    cudaEventRecord(eSpA0, 0);
    spmm_kernel<<<sp_blk_h1, 256>>>(B[0], out_xs, thA, H0_ROWS, H1_ROWS, batch, out_pool);
    cudaStreamWaitEvent(s2, eSpA0, 0);
    gemm_kernel<<<H0_GBLK, 256, 0, s2>>>(out_xs, XS_COLS, W[1], thB, 0);
    cudaEventRecord(eG1, s2);
    gemm_kernel<<<H1_GBLK, 256>>>(out_xs, XS_COLS, W[1], thB, H0_GBLK);
    cudaStreamWaitEvent(0, eG1, 0);

    // ---- layer 1 spmm (chunked, fused pool) + layer 2 gemm overlap
    spmm_kernel<<<sp_blk_h0, 256>>>(B[1], out_xs + DIM, thB, 0, H0_ROWS, batch, out_pool + DIM);
    cudaEventRecord(eSpA1, 0);
    spmm_kernel<<<sp_blk_h1, 256>>>(B[1], out_xs + DIM, thB, H0_ROWS, H1_ROWS, batch, out_pool + DIM);
    cudaStreamWaitEvent(s2, eSpA1, 0);
    gemm_kernel<<<H0_GBLK, 256, 0, s2>>>(out_xs + DIM, XS_COLS, W[2], thA, 0);
    cudaEventRecord(eG2, s2);
    gemm_kernel<<<H1_GBLK, 256>>>(out_xs + DIM, XS_COLS, W[2], thA, H0_GBLK);
    cudaStreamWaitEvent(0, eG2, 0);

    // ---- layer 2 spmm (fused pool) + finalize
    spmm_kernel<<<sp_blk_all, 256>>>(B[2], out_xs + 2 * DIM, thA, 0, N_NODES, batch, out_pool + 2 * DIM);
    finalize_kernel<<<N_GRAPHS, XS_COLS>>>(out_pool);
}

// round 16
// speedup vs baseline: 1.1491x; 1.0088x over previous
#include <cuda_runtime.h>
#include <cuda_fp16.h>
#include <cstdint>

#define N_NODES 50000
#define N_EDGES 800000
#define DIM     128
#define N_LAYERS 3
#define N_GRAPHS 128
#define TOT_E   (N_EDGES + N_NODES)   // edges + self loops
#define XS_COLS (DIM * N_LAYERS)      // 384
#define POOL_ELEMS (N_GRAPHS * XS_COLS)
#define NBLK    196                   // ceil(N_NODES/256)

// asymmetric chunking: f ~ 0.625 of 391 gemm blocks
#define H0_GBLK   244
#define H0_ROWS   (H0_GBLK * 128)        // 31232
#define H1_GBLK   147
#define H1_ROWS   (N_NODES - H0_ROWS)    // 18768

// ---------------- scratch (device globals; no allocation allowed) ----------
__device__ int   g_scratch[2 * N_NODES];       // [0:N)=deg, [N:2N)=fill
__device__ int   g_rowptr[N_NODES + 1];
__device__ int   g_colidx[TOT_E];
__device__ float g_dinv[N_NODES];
__device__ uint2 g_thA[(size_t)N_NODES * 32];  // fp16 T ping
__device__ uint2 g_thB[(size_t)N_NODES * 32];  // fp16 T pong
__device__ unsigned long long g_pub[NBLK];     // packed (flag<<32)|blocksum

// ---------------- packed f32x2 helpers -------------------------------------
__device__ __forceinline__ unsigned long long pack2(float x, float y) {
    unsigned long long r;
    asm("mov.b64 %0, {%1, %2};" : "=l"(r) : "f"(x), "f"(y));
    return r;
}
__device__ __forceinline__ void unpack2(unsigned long long v, float& lo, float& hi) {
    asm("mov.b64 {%0, %1}, %2;" : "=f"(lo), "=f"(hi) : "l"(v));
}
__device__ __forceinline__ void ffma2(unsigned long long& d,
                                      unsigned long long a,
                                      unsigned long long b) {
    asm("fma.rn.f32x2 %0, %1, %2, %0;" : "+l"(d) : "l"(a), "l"(b));
}

// ---------------- CSR build (deg counts EDGES only; +1 self loop in scan) --
// two edges per thread; also zeroes g_pub for the scan kernel
__global__ void edge_deg_kernel(const int* __restrict__ ei) {
    int e2 = blockIdx.x * blockDim.x + threadIdx.x;
    if (e2 < NBLK) g_pub[e2] = 0ULL;
    if (e2 * 2 < N_EDGES) {
        int2 d = *(const int2*)&ei[N_EDGES + e2 * 2];
        atomicAdd(&g_scratch[d.x], 1);
        if (e2 * 2 + 1 < N_EDGES) atomicAdd(&g_scratch[d.y], 1);
    }
}

// single-pass scan: local inclusive scan, publish aggregate (packed 64-bit),
// poll+sum predecessors -> base; write rowptr, dinv, self-loop colidx.
__global__ void scan_kernel() {
    __shared__ int sh[256];
    __shared__ int red[8];
    __shared__ int s_base;
    const int t = threadIdx.x;
    const int b = blockIdx.x;
    const int i = b * 256 + t;
    int v = (i < N_NODES) ? (g_scratch[i] + 1) : 0;
    sh[t] = v;
    __syncthreads();
#pragma unroll
    for (int o = 1; o < 256; o <<= 1) {
        int u = (t >= o) ? sh[t - o] : 0;
        __syncthreads();
        sh[t] += u;
        __syncthreads();
    }
    if (t == 0)
        atomicExch(&g_pub[b], 0x100000000ULL | (unsigned)sh[255]);
    // poll predecessors (t < b) and sum their aggregates
    int part = 0;
    if (t < b) {
        unsigned long long vv;
        do { vv = atomicAdd(&g_pub[t], 0ULL); } while (vv == 0ULL);
        part = (int)(vv & 0xffffffffu);
    }
#pragma unroll
    for (int o = 16; o; o >>= 1) part += __shfl_down_sync(~0u, part, o);
    if ((t & 31) == 0) red[t >> 5] = part;
    __syncthreads();
    if (t < 8) {
        int s = red[t];
#pragma unroll
        for (int o = 4; o; o >>= 1) s += __shfl_down_sync(0xffu, s, o);
        if (t == 0) s_base = s;
    }
    __syncthreads();
    int base = s_base;
    if (i < N_NODES) {
        int rp = sh[t] - v + base;
        g_rowptr[i] = rp;
        g_dinv[i]   = rsqrtf((float)v);
        g_colidx[rp] = i;                 // self loop at slot 0 of the row
    }
    if (b == 0 && t == 0) g_rowptr[N_NODES] = TOT_E;
}

// edges only; slot = rowptr[dst] + 1 + fill++
__global__ void fill_kernel(const int* __restrict__ ei) {
    int e = blockIdx.x * blockDim.x + threadIdx.x;
    if (e < N_EDGES) {
        int src = ei[e];
        int dst = ei[N_EDGES + e];
        int pos = g_rowptr[dst] + 1 + atomicAdd(&g_scratch[N_NODES + dst], 1);
        g_colidx[pos] = src;
    }
}

// ------ spmm row helper: relu(dinv*sum dinv[s]*Tin[s] + bias), 4-unrolled --
__device__ __forceinline__ float4 spmm_row(const uint2* __restrict__ th_in,
                                           int gr, int lane,
                                           const float* __restrict__ bias) {
    int e = g_rowptr[gr], end = g_rowptr[gr + 1];
    float4 acc = make_float4(0.f, 0.f, 0.f, 0.f);
    for (; e + 3 < end; e += 4) {
        int s0 = g_colidx[e];
        int s1 = g_colidx[e + 1];
        int s2 = g_colidx[e + 2];
        int s3 = g_colidx[e + 3];
        float d0 = __ldg(&g_dinv[s0]);
        float d1 = __ldg(&g_dinv[s1]);
        float d2 = __ldg(&g_dinv[s2]);
        float d3 = __ldg(&g_dinv[s3]);
        uint2 u0 = th_in[(size_t)s0 * 32 + lane];
        uint2 u1 = th_in[(size_t)s1 * 32 + lane];
        uint2 u2 = th_in[(size_t)s2 * 32 + lane];
        uint2 u3 = th_in[(size_t)s3 * 32 + lane];
        float2 a0 = __half22float2(*(__half2*)&u0.x);
        float2 b0 = __half22float2(*(__half2*)&u0.y);
        float2 a1 = __half22float2(*(__half2*)&u1.x);
        float2 b1 = __half22float2(*(__half2*)&u1.y);
        float2 a2 = __half22float2(*(__half2*)&u2.x);
        float2 b2 = __half22float2(*(__half2*)&u2.y);
        float2 a3 = __half22float2(*(__half2*)&u3.x);
        float2 b3 = __half22float2(*(__half2*)&u3.y);
        acc.x = fmaf(a0.x, d0, fmaf(a1.x, d1, fmaf(a2.x, d2, fmaf(a3.x, d3, acc.x))));
        acc.y = fmaf(a0.y, d0, fmaf(a1.y, d1, fmaf(a2.y, d2, fmaf(a3.y, d3, acc.y))));
        acc.z = fmaf(b0.x, d0, fmaf(b1.x, d1, fmaf(b2.x, d2, fmaf(b3.x, d3, acc.z))));
        acc.w = fmaf(b0.y, d0, fmaf(b1.y, d1, fmaf(b2.y, d2, fmaf(b3.y, d3, acc.w))));
    }
    for (; e < end; e++) {
        int s0 = g_colidx[e];
        float d0 = __ldg(&g_dinv[s0]);
        uint2 u0 = th_in[(size_t)s0 * 32 + lane];
        float2 a0 = __half22float2(*(__half2*)&u0.x);
        float2 b0 = __half22float2(*(__half2*)&u0.y);
        acc.x = fmaf(a0.x, d0, acc.x);
        acc.y = fmaf(a0.y, d0, acc.y);
        acc.z = fmaf(b0.x, d0, acc.z);
        acc.w = fmaf(b0.y, d0, acc.w);
    }
    float dv = g_dinv[gr];
    float4 bb = *(const float4*)&bias[lane * 4];
    float4 o;
    o.x = fmaxf(fmaf(acc.x, dv, bb.x), 0.f);
    o.y = fmaxf(fmaf(acc.y, dv, bb.y), 0.f);
    o.z = fmaxf(fmaf(acc.z, dv, bb.z), 0.f);
    o.w = fmaxf(fmaf(acc.w, dv, bb.w), 0.f);
    return o;
}

// ---------------- GEMM: T = A @ W (f32x2 FFMA, fp16 store), BK=32 ----------
__global__ __launch_bounds__(256, 2)
void gemm_kernel(const float* __restrict__ A, int lda,
                 const float* __restrict__ W, uint2* __restrict__ th_out,
                 int block_base) {
    __shared__ __align__(16) float As[32][132];
    __shared__ __align__(16) float Ws[32][128];
    const int brow = (blockIdx.x + block_base) * 128;
    const int t  = threadIdx.x;
    const int tx = t & 15;
    const int ty = t >> 4;
    unsigned long long acc2[8][4];
#pragma unroll
    for (int i = 0; i < 8; i++)
#pragma unroll
        for (int jp = 0; jp < 4; jp++) acc2[i][jp] = 0ull;

    for (int kc = 0; kc < DIM; kc += 32) {
#pragma unroll
        for (int i = 0; i < 4; i++) {
            int lin = t + i * 256;          // 0..1023
            int row = lin >> 3;             // 0..127
            int kg  = lin & 7;              // 0..7
            float4 v = make_float4(0.f, 0.f, 0.f, 0.f);
            int gr = brow + row;
            if (gr < N_NODES)
                v = *(const float4*)&A[(size_t)gr * lda + kc + kg * 4];
            As[kg * 4 + 0][row] = v.x;
            As[kg * 4 + 1][row] = v.y;
            As[kg * 4 + 2][row] = v.z;
            As[kg * 4 + 3][row] = v.w;
        }
#pragma unroll
        for (int i = 0; i < 4; i++) {
            int lin = t + i * 256;
            int kr = lin >> 5;              // 0..31
            int c4 = lin & 31;
            *(float4*)&Ws[kr][c4 * 4] =
                *(const float4*)&W[(kc + kr) * DIM + c4 * 4];
        }
        __syncthreads();
#pragma unroll
        for (int kk = 0; kk < 32; kk++) {
            float a[8];
            unsigned long long w2[4];
#pragma unroll
            for (int i = 0; i < 8; i++) a[i] = As[kk][ty * 8 + i];
#pragma unroll
            for (int jp = 0; jp < 4; jp++)
                w2[jp] = *(const unsigned long long*)&Ws[kk][tx * 8 + jp * 2];
#pragma unroll
            for (int i = 0; i < 8; i++) {
                unsigned long long a2 = pack2(a[i], a[i]);
#pragma unroll
                for (int jp = 0; jp < 4; jp++)
                    ffma2(acc2[i][jp], a2, w2[jp]);
            }
        }
        __syncthreads();
    }
#pragma unroll
    for (int i = 0; i < 8; i++) {
        int gr = brow + ty * 8 + i;
        if (gr < N_NODES) {
            float2 f01, f23, f45, f67;
            unpack2(acc2[i][0], f01.x, f01.y);
            unpack2(acc2[i][1], f23.x, f23.y);
            unpack2(acc2[i][2], f45.x, f45.y);
            unpack2(acc2[i][3], f67.x, f67.y);
            __half2 h0 = __float22half2_rn(f01);
            __half2 h1 = __float22half2_rn(f23);
            __half2 h2 = __float22half2_rn(f45);
            __half2 h3 = __float22half2_rn(f67);
            uint4 st;
            st.x = *(unsigned*)&h0;
            st.y = *(unsigned*)&h1;
            st.z = *(unsigned*)&h2;
            st.w = *(unsigned*)&h3;
            *(uint4*)&th_out[(size_t)gr * 32 + tx * 2] = st;
        }
    }
}

// ------- SpMM with fused pooling: 8 warps = 8 rows per block ---------------
__global__ void spmm_kernel(const float* __restrict__ bias,
                            float* __restrict__ out,
                            const uint2* __restrict__ th_in,
                            int row_base, int n_rows,
                            const int* __restrict__ batch,
                            float* __restrict__ pool_slice) {
    __shared__ float ps[8][128];
    __shared__ int   bg[8];
    const int wid  = threadIdx.x >> 5;
    const int lane = threadIdx.x & 31;
    const int w    = blockIdx.x * 8 + wid;
    const bool valid = (w < n_rows);
    float4 o = make_float4(0.f, 0.f, 0.f, 0.f);
    if (valid) {
        int gr = row_base + w;
        o = spmm_row(th_in, gr, lane, bias);
        *(float4*)&out[(size_t)gr * XS_COLS + lane * 4] = o;
        if (lane == 0) bg[wid] = batch[gr];
    } else if (lane == 0) {
        bg[wid] = -1;
    }
    *(float4*)&ps[wid][lane * 4] = o;
    __syncthreads();
    if (threadIdx.x < 128) {
        int f = threadIdx.x;
        int g0 = bg[0];
        bool uni = (g0 >= 0);
#pragma unroll
        for (int r = 1; r < 8; r++) uni = uni && (bg[r] == g0);
        if (uni) {
            float s = 0.f;
#pragma unroll
            for (int r = 0; r < 8; r++) s += ps[r][f];
            atomicAdd(&pool_slice[(size_t)g0 * XS_COLS + f], s);
        } else {
#pragma unroll
            for (int r = 0; r < 8; r++)
                if (bg[r] >= 0)
                    atomicAdd(&pool_slice[(size_t)bg[r] * XS_COLS + f], ps[r][f]);
        }
    }
}

// -------- finalize: bounds by binary search, divide pool sums --------------
__global__ void finalize_kernel(const int* __restrict__ batch,
                                float* __restrict__ out_pool) {
    __shared__ int s_lo, s_hi;
    int g = blockIdx.x;
    int f = threadIdx.x;      // 0..383
    if (f < 2) {
        int target = g + f;
        int lo = 0, hi = N_NODES;
        while (lo < hi) {
            int mid = (lo + hi) >> 1;
            if (batch[mid] < target) lo = mid + 1; else hi = mid;
        }
        if (f == 0) s_lo = lo; else s_hi = lo;
    }
    __syncthreads();
    float cnt = (float)max(s_hi - s_lo, 1);
    out_pool[(size_t)g * XS_COLS + f] /= cnt;
}

// ---------------- launch ---------------------------------------------------
extern "C" void kernel_launch(void* const* d_in, const int* in_sizes, int n_in,
                              void* d_out, int out_size) {
    const float* x     = (const float*)d_in[0];
    const int*   ei    = (const int*)d_in[1];     // int32 (JAX x64 disabled)
    const int*   batch = (const int*)d_in[2];     // int32
    const float* W[3] = { (const float*)d_in[3], (const float*)d_in[5],
                          (const float*)d_in[7] };
    const float* B[3] = { (const float*)d_in[4], (const float*)d_in[6],
                          (const float*)d_in[8] };
    float* out_pool = (float*)d_out;
    float* out_xs   = (float*)d_out + POOL_ELEMS;

    static cudaStream_t s2 = nullptr;
    static cudaEvent_t evF = nullptr, evJ = nullptr;
    static cudaEvent_t eSpA0 = nullptr, eSpA1 = nullptr;
    static cudaEvent_t eG1 = nullptr, eG2 = nullptr;
    static void *p_scr = nullptr;
    static uint2 *thA = nullptr, *thB = nullptr;
    if (!s2) {
        cudaStreamCreateWithFlags(&s2, cudaStreamNonBlocking);
        cudaEventCreateWithFlags(&evF,   cudaEventDisableTiming);
        cudaEventCreateWithFlags(&evJ,   cudaEventDisableTiming);
        cudaEventCreateWithFlags(&eSpA0, cudaEventDisableTiming);
        cudaEventCreateWithFlags(&eSpA1, cudaEventDisableTiming);
        cudaEventCreateWithFlags(&eG1,   cudaEventDisableTiming);
        cudaEventCreateWithFlags(&eG2,   cudaEventDisableTiming);
        cudaGetSymbolAddress(&p_scr, g_scratch);
        void* p;
        cudaGetSymbolAddress(&p, g_thA); thA = (uint2*)p;
        cudaGetSymbolAddress(&p, g_thB); thB = (uint2*)p;
    }

    const int gemm_blocks = (N_NODES + 127) / 128;           // 391
    const int sp_blk_h0 = (H0_ROWS + 7) / 8;                 // 3904
    const int sp_blk_h1 = (H1_ROWS + 7) / 8;                 // 2346
    const int sp_blk_all = (N_NODES + 7) / 8;                // 6250

    // fork: pool-zero + layer-0 GEMM (independent of CSR) on s2
    cudaEventRecord(evF, 0);
    cudaStreamWaitEvent(s2, evF, 0);
    cudaMemsetAsync(out_pool, 0, POOL_ELEMS * sizeof(float), s2);
    gemm_kernel<<<gemm_blocks, 256, 0, s2>>>(x, DIM, W[0], thA, 0);

    // CSR build on the capture stream
    cudaMemsetAsync(p_scr, 0, 2 * N_NODES * sizeof(int), 0);
    edge_deg_kernel<<<(N_EDGES / 2 + 255) / 256, 256>>>(ei);
    scan_kernel<<<NBLK, 256>>>();
    fill_kernel<<<(N_EDGES + 255) / 256, 256>>>(ei);

    // join gemm0 (also orders pool memset before first spmm)
    cudaEventRecord(evJ, s2);
    cudaStreamWaitEvent(0, evJ, 0);

    // ---- layer 0 spmm (chunked, fused pool) + layer 1 gemm overlap
    spmm_kernel<<<sp_blk_h0, 256>>>(B[0], out_xs, thA, 0, H0_ROWS, batch, out_pool);
    cudaEventRecord(eSpA0, 0);
    spmm_kernel<<<sp_blk_h1, 256>>>(B[0], out_xs, thA, H0_ROWS, H1_ROWS, batch, out_pool);
    cudaStreamWaitEvent(s2, eSpA0, 0);
    gemm_kernel<<<H0_GBLK, 256, 0, s2>>>(out_xs, XS_COLS, W[1], thB, 0);
    cudaEventRecord(eG1, s2);
    gemm_kernel<<<H1_GBLK, 256>>>(out_xs, XS_COLS, W[1], thB, H0_GBLK);
    cudaStreamWaitEvent(0, eG1, 0);

    // ---- layer 1 spmm (chunked, fused pool) + layer 2 gemm overlap
    spmm_kernel<<<sp_blk_h0, 256>>>(B[1], out_xs + DIM, thB, 0, H0_ROWS, batch, out_pool + DIM);
    cudaEventRecord(eSpA1, 0);
    spmm_kernel<<<sp_blk_h1, 256>>>(B[1], out_xs + DIM, thB, H0_ROWS, H1_ROWS, batch, out_pool + DIM);
    cudaStreamWaitEvent(s2, eSpA1, 0);
    gemm_kernel<<<H0_GBLK, 256, 0, s2>>>(out_xs + DIM, XS_COLS, W[2], thA, 0);
    cudaEventRecord(eG2, s2);
    gemm_kernel<<<H1_GBLK, 256>>>(out_xs + DIM, XS_COLS, W[2], thA, H0_GBLK);
    cudaStreamWaitEvent(0, eG2, 0);

    // ---- layer 2 spmm (fused pool) + finalize
    spmm_kernel<<<sp_blk_all, 256>>>(B[2], out_xs + 2 * DIM, thA, 0, N_NODES, batch, out_pool + 2 * DIM);
    finalize_kernel<<<N_GRAPHS, XS_COLS>>>(batch, out_pool);
}

// round 17
// speedup vs baseline: 1.1594x; 1.0090x over previous
#include <cuda_runtime.h>
#include <cuda_fp16.h>
#include <cstdint>

#define N_NODES 50000
#define N_EDGES 800000
#define DIM     128
#define N_LAYERS 3
#define N_GRAPHS 128
#define TOT_E   (N_EDGES + N_NODES)   // edges + self loops
#define XS_COLS (DIM * N_LAYERS)      // 384
#define POOL_ELEMS (N_GRAPHS * XS_COLS)
#define NBLK    196                   // ceil(N_NODES/256)

// asymmetric chunking: f ~ 0.625 of 391 gemm blocks
#define H0_GBLK   244
#define H0_ROWS   (H0_GBLK * 128)        // 31232
#define H1_GBLK   147
#define H1_ROWS   (N_NODES - H0_ROWS)    // 18768

// ---------------- scratch (device globals; no allocation allowed) ----------
__device__ int   g_deg[N_NODES];
__device__ int   g_rank[N_EDGES];              // per-edge rank within dst row
__device__ int   g_rowptr[N_NODES + 1];
__device__ int   g_colidx[TOT_E];
__device__ float g_dinv[N_NODES];
__device__ uint2 g_thA[(size_t)N_NODES * 32];  // fp16 T ping
__device__ uint2 g_thB[(size_t)N_NODES * 32];  // fp16 T pong
__device__ unsigned long long g_pub[NBLK];     // packed (flag<<32)|blocksum

// ---------------- packed f32x2 helpers -------------------------------------
__device__ __forceinline__ unsigned long long pack2(float x, float y) {
    unsigned long long r;
    asm("mov.b64 %0, {%1, %2};" : "=l"(r) : "f"(x), "f"(y));
    return r;
}
__device__ __forceinline__ void unpack2(unsigned long long v, float& lo, float& hi) {
    asm("mov.b64 {%0, %1}, %2;" : "=f"(lo), "=f"(hi) : "l"(v));
}
__device__ __forceinline__ void ffma2(unsigned long long& d,
                                      unsigned long long a,
                                      unsigned long long b) {
    asm("fma.rn.f32x2 %0, %1, %2, %0;" : "+l"(d) : "l"(a), "l"(b));
}

// ---- CSR build: count degrees AND record each edge's rank ticket ----------
__global__ void edge_deg_kernel(const int* __restrict__ ei) {
    int e2 = blockIdx.x * blockDim.x + threadIdx.x;
    if (e2 < NBLK) g_pub[e2] = 0ULL;
    if (e2 * 2 < N_EDGES) {
        int2 d = *(const int2*)&ei[N_EDGES + e2 * 2];
        int r0 = atomicAdd(&g_deg[d.x], 1);
        g_rank[e2 * 2] = r0;
        if (e2 * 2 + 1 < N_EDGES) {
            int r1 = atomicAdd(&g_deg[d.y], 1);
            g_rank[e2 * 2 + 1] = r1;
        }
    }
}

// single-pass scan: local inclusive scan, publish aggregate (packed 64-bit),
// poll+sum predecessors -> base; write rowptr, dinv, self-loop colidx.
__global__ void scan_kernel() {
    __shared__ int sh[256];
    __shared__ int red[8];
    __shared__ int s_base;
    const int t = threadIdx.x;
    const int b = blockIdx.x;
    const int i = b * 256 + t;
    int v = (i < N_NODES) ? (g_deg[i] + 1) : 0;
    sh[t] = v;
    __syncthreads();
#pragma unroll
    for (int o = 1; o < 256; o <<= 1) {
        int u = (t >= o) ? sh[t - o] : 0;
        __syncthreads();
        sh[t] += u;
        __syncthreads();
    }
    if (t == 0)
        atomicExch(&g_pub[b], 0x100000000ULL | (unsigned)sh[255]);
    // poll predecessors (t < b) and sum their aggregates
    int part = 0;
    if (t < b) {
        unsigned long long vv;
        do { vv = atomicAdd(&g_pub[t], 0ULL); } while (vv == 0ULL);
        part = (int)(vv & 0xffffffffu);
    }
#pragma unroll
    for (int o = 16; o; o >>= 1) part += __shfl_down_sync(~0u, part, o);
    if ((t & 31) == 0) red[t >> 5] = part;
    __syncthreads();
    if (t < 8) {
        int s = red[t];
#pragma unroll
        for (int o = 4; o; o >>= 1) s += __shfl_down_sync(0xffu, s, o);
        if (t == 0) s_base = s;
    }
    __syncthreads();
    int base = s_base;
    if (i < N_NODES) {
        int rp = sh[t] - v + base;
        g_rowptr[i] = rp;
        g_dinv[i]   = rsqrtf((float)v);
        g_colidx[rp] = i;                 // self loop at slot 0 of the row
    }
    if (b == 0 && t == 0) g_rowptr[N_NODES] = TOT_E;
}

// atomic-free fill: pos = rowptr[dst] + 1 + rank[e]
__global__ void fill_kernel(const int* __restrict__ ei) {
    int e = blockIdx.x * blockDim.x + threadIdx.x;
    if (e < N_EDGES) {
        int src = ei[e];
        int dst = ei[N_EDGES + e];
        int pos = g_rowptr[dst] + 1 + g_rank[e];
        g_colidx[pos] = src;
    }
}

// ------ spmm row helper: relu(dinv*sum dinv[s]*Tin[s] + bias), 4-unrolled --
__device__ __forceinline__ float4 spmm_row(const uint2* __restrict__ th_in,
                                           int gr, int lane,
                                           const float* __restrict__ bias) {
    int e = g_rowptr[gr], end = g_rowptr[gr + 1];
    float4 acc = make_float4(0.f, 0.f, 0.f, 0.f);
    for (; e + 3 < end; e += 4) {
        int s0 = g_colidx[e];
        int s1 = g_colidx[e + 1];
        int s2 = g_colidx[e + 2];
        int s3 = g_colidx[e + 3];
        float d0 = __ldg(&g_dinv[s0]);
        float d1 = __ldg(&g_dinv[s1]);
        float d2 = __ldg(&g_dinv[s2]);
        float d3 = __ldg(&g_dinv[s3]);
        uint2 u0 = th_in[(size_t)s0 * 32 + lane];
        uint2 u1 = th_in[(size_t)s1 * 32 + lane];
        uint2 u2 = th_in[(size_t)s2 * 32 + lane];
        uint2 u3 = th_in[(size_t)s3 * 32 + lane];
        float2 a0 = __half22float2(*(__half2*)&u0.x);
        float2 b0 = __half22float2(*(__half2*)&u0.y);
        float2 a1 = __half22float2(*(__half2*)&u1.x);
        float2 b1 = __half22float2(*(__half2*)&u1.y);
        float2 a2 = __half22float2(*(__half2*)&u2.x);
        float2 b2 = __half22float2(*(__half2*)&u2.y);
        float2 a3 = __half22float2(*(__half2*)&u3.x);
        float2 b3 = __half22float2(*(__half2*)&u3.y);
        acc.x = fmaf(a0.x, d0, fmaf(a1.x, d1, fmaf(a2.x, d2, fmaf(a3.x, d3, acc.x))));
        acc.y = fmaf(a0.y, d0, fmaf(a1.y, d1, fmaf(a2.y, d2, fmaf(a3.y, d3, acc.y))));
        acc.z = fmaf(b0.x, d0, fmaf(b1.x, d1, fmaf(b2.x, d2, fmaf(b3.x, d3, acc.z))));
        acc.w = fmaf(b0.y, d0, fmaf(b1.y, d1, fmaf(b2.y, d2, fmaf(b3.y, d3, acc.w))));
    }
    for (; e < end; e++) {
        int s0 = g_colidx[e];
        float d0 = __ldg(&g_dinv[s0]);
        uint2 u0 = th_in[(size_t)s0 * 32 + lane];
        float2 a0 = __half22float2(*(__half2*)&u0.x);
        float2 b0 = __half22float2(*(__half2*)&u0.y);
        acc.x = fmaf(a0.x, d0, acc.x);
        acc.y = fmaf(a0.y, d0, acc.y);
        acc.z = fmaf(b0.x, d0, acc.z);
        acc.w = fmaf(b0.y, d0, acc.w);
    }
    float dv = g_dinv[gr];
    float4 bb = *(const float4*)&bias[lane * 4];
    float4 o;
    o.x = fmaxf(fmaf(acc.x, dv, bb.x), 0.f);
    o.y = fmaxf(fmaf(acc.y, dv, bb.y), 0.f);
    o.z = fmaxf(fmaf(acc.z, dv, bb.z), 0.f);
    o.w = fmaxf(fmaf(acc.w, dv, bb.w), 0.f);
    return o;
}

// ---------------- GEMM: T = A @ W (f32x2 FFMA, fp16 store), BK=32 ----------
__global__ __launch_bounds__(256, 2)
void gemm_kernel(const float* __restrict__ A, int lda,
                 const float* __restrict__ W, uint2* __restrict__ th_out,
                 int block_base) {
    __shared__ __align__(16) float As[32][132];
    __shared__ __align__(16) float Ws[32][128];
    const int brow = (blockIdx.x + block_base) * 128;
    const int t  = threadIdx.x;
    const int tx = t & 15;
    const int ty = t >> 4;
    unsigned long long acc2[8][4];
#pragma unroll
    for (int i = 0; i < 8; i++)
#pragma unroll
        for (int jp = 0; jp < 4; jp++) acc2[i][jp] = 0ull;

    for (int kc = 0; kc < DIM; kc += 32) {
#pragma unroll
        for (int i = 0; i < 4; i++) {
            int lin = t + i * 256;          // 0..1023
            int row = lin >> 3;             // 0..127
            int kg  = lin & 7;              // 0..7
            float4 v = make_float4(0.f, 0.f, 0.f, 0.f);
            int gr = brow + row;
            if (gr < N_NODES)
                v = *(const float4*)&A[(size_t)gr * lda + kc + kg * 4];
            As[kg * 4 + 0][row] = v.x;
            As[kg * 4 + 1][row] = v.y;
            As[kg * 4 + 2][row] = v.z;
            As[kg * 4 + 3][row] = v.w;
        }
#pragma unroll
        for (int i = 0; i < 4; i++) {
            int lin = t + i * 256;
            int kr = lin >> 5;              // 0..31
            int c4 = lin & 31;
            *(float4*)&Ws[kr][c4 * 4] =
                *(const float4*)&W[(kc + kr) * DIM + c4 * 4];
        }
        __syncthreads();
#pragma unroll
        for (int kk = 0; kk < 32; kk++) {
            float a[8];
            unsigned long long w2[4];
#pragma unroll
            for (int i = 0; i < 8; i++) a[i] = As[kk][ty * 8 + i];
#pragma unroll
            for (int jp = 0; jp < 4; jp++)
                w2[jp] = *(const unsigned long long*)&Ws[kk][tx * 8 + jp * 2];
#pragma unroll
            for (int i = 0; i < 8; i++) {
                unsigned long long a2 = pack2(a[i], a[i]);
#pragma unroll
                for (int jp = 0; jp < 4; jp++)
                    ffma2(acc2[i][jp], a2, w2[jp]);
            }
        }
        __syncthreads();
    }
#pragma unroll
    for (int i = 0; i < 8; i++) {
        int gr = brow + ty * 8 + i;
        if (gr < N_NODES) {
            float2 f01, f23, f45, f67;
            unpack2(acc2[i][0], f01.x, f01.y);
            unpack2(acc2[i][1], f23.x, f23.y);
            unpack2(acc2[i][2], f45.x, f45.y);
            unpack2(acc2[i][3], f67.x, f67.y);
            __half2 h0 = __float22half2_rn(f01);
            __half2 h1 = __float22half2_rn(f23);
            __half2 h2 = __float22half2_rn(f45);
            __half2 h3 = __float22half2_rn(f67);
            uint4 st;
            st.x = *(unsigned*)&h0;
            st.y = *(unsigned*)&h1;
            st.z = *(unsigned*)&h2;
            st.w = *(unsigned*)&h3;
            *(uint4*)&th_out[(size_t)gr * 32 + tx * 2] = st;
        }
    }
}

// ------- SpMM with fused pooling: 8 warps = 8 rows per block ---------------
__global__ void spmm_kernel(const float* __restrict__ bias,
                            float* __restrict__ out,
                            const uint2* __restrict__ th_in,
                            int row_base, int n_rows,
                            const int* __restrict__ batch,
                            float* __restrict__ pool_slice) {
    __shared__ float ps[8][128];
    __shared__ int   bg[8];
    const int wid  = threadIdx.x >> 5;
    const int lane = threadIdx.x & 31;
    const int w    = blockIdx.x * 8 + wid;
    const bool valid = (w < n_rows);
    float4 o = make_float4(0.f, 0.f, 0.f, 0.f);
    if (valid) {
        int gr = row_base + w;
        o = spmm_row(th_in, gr, lane, bias);
        *(float4*)&out[(size_t)gr * XS_COLS + lane * 4] = o;
        if (lane == 0) bg[wid] = batch[gr];
    } else if (lane == 0) {
        bg[wid] = -1;
    }
    *(float4*)&ps[wid][lane * 4] = o;
    __syncthreads();
    if (threadIdx.x < 128) {
        int f = threadIdx.x;
        int g0 = bg[0];
        bool uni = (g0 >= 0);
#pragma unroll
        for (int r = 1; r < 8; r++) uni = uni && (bg[r] == g0);
        if (uni) {
            float s = 0.f;
#pragma unroll
            for (int r = 0; r < 8; r++) s += ps[r][f];
            atomicAdd(&pool_slice[(size_t)g0 * XS_COLS + f], s);
        } else {
#pragma unroll
            for (int r = 0; r < 8; r++)
                if (bg[r] >= 0)
                    atomicAdd(&pool_slice[(size_t)bg[r] * XS_COLS + f], ps[r][f]);
        }
    }
}

// -------- finalize: bounds by binary search, divide pool sums --------------
__global__ void finalize_kernel(const int* __restrict__ batch,
                                float* __restrict__ out_pool) {
    __shared__ int s_lo, s_hi;
    int g = blockIdx.x;
    int f = threadIdx.x;      // 0..383
    if (f < 2) {
        int target = g + f;
        int lo = 0, hi = N_NODES;
        while (lo < hi) {
            int mid = (lo + hi) >> 1;
            if (batch[mid] < target) lo = mid + 1; else hi = mid;
        }
        if (f == 0) s_lo = lo; else s_hi = lo;
    }
    __syncthreads();
    float cnt = (float)max(s_hi - s_lo, 1);
    out_pool[(size_t)g * XS_COLS + f] /= cnt;
}

// ---------------- launch ---------------------------------------------------
extern "C" void kernel_launch(void* const* d_in, const int* in_sizes, int n_in,
                              void* d_out, int out_size) {
    const float* x     = (const float*)d_in[0];
    const int*   ei    = (const int*)d_in[1];     // int32 (JAX x64 disabled)
    const int*   batch = (const int*)d_in[2];     // int32
    const float* W[3] = { (const float*)d_in[3], (const float*)d_in[5],
                          (const float*)d_in[7] };
    const float* B[3] = { (const float*)d_in[4], (const float*)d_in[6],
                          (const float*)d_in[8] };
    float* out_pool = (float*)d_out;
    float* out_xs   = (float*)d_out + POOL_ELEMS;

    static cudaStream_t s2 = nullptr;
    static cudaEvent_t evF = nullptr, evJ = nullptr;
    static cudaEvent_t eSpA0 = nullptr, eSpA1 = nullptr;
    static cudaEvent_t eG1 = nullptr, eG2 = nullptr;
    static void *p_deg = nullptr;
    static uint2 *thA = nullptr, *thB = nullptr;
    if (!s2) {
        cudaStreamCreateWithFlags(&s2, cudaStreamNonBlocking);
        cudaEventCreateWithFlags(&evF,   cudaEventDisableTiming);
        cudaEventCreateWithFlags(&evJ,   cudaEventDisableTiming);
        cudaEventCreateWithFlags(&eSpA0, cudaEventDisableTiming);
        cudaEventCreateWithFlags(&eSpA1, cudaEventDisableTiming);
        cudaEventCreateWithFlags(&eG1,   cudaEventDisableTiming);
        cudaEventCreateWithFlags(&eG2,   cudaEventDisableTiming);
        cudaGetSymbolAddress(&p_deg, g_deg);
        void* p;
        cudaGetSymbolAddress(&p, g_thA); thA = (uint2*)p;
        cudaGetSymbolAddress(&p, g_thB); thB = (uint2*)p;
    }

    const int gemm_blocks = (N_NODES + 127) / 128;           // 391
    const int sp_blk_h0 = (H0_ROWS + 7) / 8;                 // 3904
    const int sp_blk_h1 = (H1_ROWS + 7) / 8;                 // 2346
    const int sp_blk_all = (N_NODES + 7) / 8;                // 6250

    // fork: pool-zero + layer-0 GEMM (independent of CSR) on s2
    cudaEventRecord(evF, 0);
    cudaStreamWaitEvent(s2, evF, 0);
    cudaMemsetAsync(out_pool, 0, POOL_ELEMS * sizeof(float), s2);
    gemm_kernel<<<gemm_blocks, 256, 0, s2>>>(x, DIM, W[0], thA, 0);

    // CSR build on the capture stream
    cudaMemsetAsync(p_deg, 0, N_NODES * sizeof(int), 0);
    edge_deg_kernel<<<(N_EDGES / 2 + 255) / 256, 256>>>(ei);
    scan_kernel<<<NBLK, 256>>>();
    fill_kernel<<<(N_EDGES + 255) / 256, 256>>>(ei);

    // join gemm0 (also orders pool memset before first spmm)
    cudaEventRecord(evJ, s2);
    cudaStreamWaitEvent(0, evJ, 0);

    // ---- layer 0 spmm (chunked, fused pool) + layer 1 gemm overlap
    spmm_kernel<<<sp_blk_h0, 256>>>(B[0], out_xs, thA, 0, H0_ROWS, batch, out_pool);
    cudaEventRecord(eSpA0, 0);
    spmm_kernel<<<sp_blk_h1, 256>>>(B[0], out_xs, thA, H0_ROWS, H1_ROWS, batch, out_pool);
    cudaStreamWaitEvent(s2, eSpA0, 0);
    gemm_kernel<<<H0_GBLK, 256, 0, s2>>>(out_xs, XS_COLS, W[1], thB, 0);
    cudaEventRecord(eG1, s2);
    gemm_kernel<<<H1_GBLK, 256>>>(out_xs, XS_COLS, W[1], thB, H0_GBLK);
    cudaStreamWaitEvent(0, eG1, 0);

    // ---- layer 1 spmm (chunked, fused pool) + layer 2 gemm overlap
    spmm_kernel<<<sp_blk_h0, 256>>>(B[1], out_xs + DIM, thB, 0, H0_ROWS, batch, out_pool + DIM);
    cudaEventRecord(eSpA1, 0);
    spmm_kernel<<<sp_blk_h1, 256>>>(B[1], out_xs + DIM, thB, H0_ROWS, H1_ROWS, batch, out_pool + DIM);
    cudaStreamWaitEvent(s2, eSpA1, 0);
    gemm_kernel<<<H0_GBLK, 256, 0, s2>>>(out_xs + DIM, XS_COLS, W[2], thA, 0);
    cudaEventRecord(eG2, s2);
    gemm_kernel<<<H1_GBLK, 256>>>(out_xs + DIM, XS_COLS, W[2], thA, H0_GBLK);
    cudaStreamWaitEvent(0, eG2, 0);

    // ---- layer 2 spmm (fused pool) + finalize
    spmm_kernel<<<sp_blk_all, 256>>>(B[2], out_xs + 2 * DIM, thA, 0, N_NODES, batch, out_pool + 2 * DIM);
    finalize_kernel<<<N_GRAPHS, XS_COLS>>>(batch, out_pool);
}